// round 2
// baseline (speedup 1.0000x reference)
#include <cuda_runtime.h>

// Problem constants
#define HW     262144        // 512*512
#define NB_B   2
#define NCH    48
#define NC3    144
#define NHEADS 8

// Scratch (device globals: no allocation allowed)
__device__ float g_qkv[NB_B * NC3 * HW];     // after 1x1 qkv conv
__device__ float g_dw[NB_B * NC3 * HW];      // after depthwise 3x3
__device__ float g_ao[NB_B * NCH * HW];      // after attn@V (from_blocks layout)
__device__ float g_norm2[NB_B * 96 * 16];    // per (b, q/k-channel, y%4, x%4) sum sq
__device__ float g_S[NB_B * NHEADS * 96 * 96]; // gram -> softmaxed attn

typedef unsigned long long u64;

__device__ __forceinline__ void fma2(u64& d, u64 a, u64 b) {
    asm("fma.rn.f32x2 %0, %1, %2, %0;" : "+l"(d) : "l"(a), "l"(b));
}
__device__ __forceinline__ u64 pk2(float lo, float hi) {
    u64 r; asm("mov.b64 %0, {%1, %2};" : "=l"(r) : "f"(lo), "f"(hi)); return r;
}
__device__ __forceinline__ float hsum(u64 v) {
    float lo, hi; asm("mov.b64 {%0, %1}, %2;" : "=f"(lo), "=f"(hi) : "l"(v)); return lo + hi;
}
__device__ __forceinline__ void up2(u64 v, float& lo, float& hi) {
    asm("mov.b64 {%0, %1}, %2;" : "=f"(lo), "=f"(hi) : "l"(v));
}

// ---------------------------------------------------------------------------
// K0: zero the accumulation buffers
// ---------------------------------------------------------------------------
__global__ void k_zero() {
    int i = blockIdx.x * 256 + threadIdx.x;
    if (i < NB_B * NHEADS * 96 * 96) g_S[i] = 0.f;
    if (i < NB_B * 96 * 16)          g_norm2[i] = 0.f;
}

// ---------------------------------------------------------------------------
// K1: 1x1 conv 48 -> 144, 2 pixels per thread (weights amortized)
// grid 1024 x 256 thr; pixels p0 = blk*512 + tid, p1 = p0 + 256
// ---------------------------------------------------------------------------
__global__ void __launch_bounds__(256) k_qkv(const float* __restrict__ x,
                                             const float* __restrict__ w) {
    __shared__ __align__(16) float ws[NC3 * NCH];
    int tid = threadIdx.x;
    for (int e = tid; e < NC3 * NCH; e += 256) ws[e] = w[e];
    __syncthreads();

    int p0 = blockIdx.x * 512 + tid;
    int b = p0 >> 18;
    int q = p0 & (HW - 1);
    const float* xb = x + b * (NCH * HW) + q;

    u64 xp0[24], xp1[24];
#pragma unroll
    for (int j = 0; j < 24; j++) {
        xp0[j] = pk2(xb[(2 * j) * HW], xb[(2 * j + 1) * HW]);
        xp1[j] = pk2(xb[(2 * j) * HW + 256], xb[(2 * j + 1) * HW + 256]);
    }

    float* op = g_qkv + b * (NC3 * HW) + q;
    const ulonglong2* w2 = (const ulonglong2*)ws;
    for (int oc = 0; oc < NC3; oc++) {
        const ulonglong2* wr = w2 + oc * 12;
        u64 a0 = 0, a1 = 0, a2 = 0, a3 = 0;
        u64 c0 = 0, c1 = 0, c2 = 0, c3 = 0;
#pragma unroll
        for (int j = 0; j < 12; j += 2) {
            ulonglong2 wa = wr[j];
            ulonglong2 wb = wr[j + 1];
            fma2(a0, wa.x, xp0[2 * j + 0]);
            fma2(a1, wa.y, xp0[2 * j + 1]);
            fma2(a2, wb.x, xp0[2 * j + 2]);
            fma2(a3, wb.y, xp0[2 * j + 3]);
            fma2(c0, wa.x, xp1[2 * j + 0]);
            fma2(c1, wa.y, xp1[2 * j + 1]);
            fma2(c2, wb.x, xp1[2 * j + 2]);
            fma2(c3, wb.y, xp1[2 * j + 3]);
        }
        op[oc * HW]       = hsum(a0) + hsum(a1) + hsum(a2) + hsum(a3);
        op[oc * HW + 256] = hsum(c0) + hsum(c1) + hsum(c2) + hsum(c3);
    }
}

// ---------------------------------------------------------------------------
// K2: depthwise 3x3 (zero pad) + fused q/k squared-norm accumulation
// ---------------------------------------------------------------------------
__global__ void __launch_bounds__(128) k_dw(const float* __restrict__ dww) {
    int ch = blockIdx.z % NC3;
    int b  = blockIdx.z / NC3;
    __shared__ float wk[9];
    __shared__ float sb[16];
    int tid = threadIdx.y * 16 + threadIdx.x;
    if (tid < 9)  wk[tid] = dww[ch * 9 + tid];
    if (tid < 16) sb[tid] = 0.f;
    __syncthreads();

    int x0 = (blockIdx.x * 16 + threadIdx.x) * 4;
    int y0 = blockIdx.y * 8 + threadIdx.y;
    const float* in = g_qkv + (b * NC3 + ch) * HW;

    float v[3][6];
#pragma unroll
    for (int r = 0; r < 3; r++) {
        int y = y0 + r - 1;
        if (y >= 0 && y < 512) {
            const float* rp = in + y * 512;
            float4 m = *(const float4*)(rp + x0);
            v[r][0] = (x0 > 0) ? rp[x0 - 1] : 0.f;
            v[r][1] = m.x; v[r][2] = m.y; v[r][3] = m.z; v[r][4] = m.w;
            v[r][5] = (x0 + 4 < 512) ? rp[x0 + 4] : 0.f;
        } else {
#pragma unroll
            for (int c = 0; c < 6; c++) v[r][c] = 0.f;
        }
    }

    float o[4];
#pragma unroll
    for (int px = 0; px < 4; px++) {
        float s = 0.f;
#pragma unroll
        for (int r = 0; r < 3; r++)
#pragma unroll
            for (int c = 0; c < 3; c++)
                s += wk[r * 3 + c] * v[r][px + c];
        o[px] = s;
    }
    float4 ov = make_float4(o[0], o[1], o[2], o[3]);
    *(float4*)(g_dw + (b * NC3 + ch) * HW + y0 * 512 + x0) = ov;

    if (ch < 96) {
#pragma unroll
        for (int px = 0; px < 4; px++) {
            float s = o[px] * o[px];
            s += __shfl_xor_sync(0xffffffffu, s, 8);
            s += __shfl_xor_sync(0xffffffffu, s, 4);
            s += __shfl_xor_sync(0xffffffffu, s, 2);
            s += __shfl_xor_sync(0xffffffffu, s, 1);
            if ((tid & 15) == 0) atomicAdd(&sb[(y0 & 3) * 4 + px], s);
        }
        __syncthreads();
        if (tid < 16) atomicAdd(&g_norm2[(b * 96 + ch) * 16 + tid], sb[tid]);
    }
}

// ---------------------------------------------------------------------------
// K3: raw gram  S[b,h,r,d] = sum_n q_r[n] * k_d[n]
// grid (64 chunks x 16 bh); 256 thr, 2 blocks/SM, reg double-buffered loads
// ---------------------------------------------------------------------------
__global__ void __launch_bounds__(256, 2) k_gram() {
    int bh = blockIdx.y;
    int b = bh >> 3, h = bh & 7;
    int chunk = blockIdx.x;                  // 256 columns per chunk, 16 steps
    __shared__ __align__(16) float qs[96 * 18];
    __shared__ __align__(16) float ks[96 * 18];
    int tid = threadIdx.x;
    int ty = tid >> 4, tx = tid & 15;
    int kk = tid & 15;

    const float* qb = g_dw + (b * NC3 + h * 6) * HW;
    const float* kb = qb + 48 * HW;

    int offs[6];
#pragma unroll
    for (int u = 0; u < 6; u++) {
        int row = u * 16 + ty;
        int cc = row >> 4, nh = (row >> 2) & 3, nw = row & 3;
        offs[u] = cc * HW + nh * 512 + nw + 4 * kk;
    }

    u64 A[36];
#pragma unroll
    for (int e = 0; e < 36; e++) A[e] = 0;

    float rq[6], rk[6];
    {
        int so = (2 * chunk) * 2048;         // step 0
#pragma unroll
        for (int u = 0; u < 6; u++) {
            rq[u] = qb[offs[u] + so];
            rk[u] = kb[offs[u] + so];
        }
    }

    for (int s = 0; s < 16; s++) {
#pragma unroll
        for (int u = 0; u < 6; u++) {
            int sidx = (u * 16 + ty) * 18 + kk;
            qs[sidx] = rq[u];
            ks[sidx] = rk[u];
        }
        __syncthreads();
        if (s < 15) {
            int s1 = s + 1;
            int so1 = (2 * chunk + (s1 >> 3)) * 2048 + (s1 & 7) * 64;
#pragma unroll
            for (int u = 0; u < 6; u++) {
                rq[u] = qb[offs[u] + so1];
                rk[u] = kb[offs[u] + so1];
            }
        }
#pragma unroll
        for (int k2 = 0; k2 < 8; k2++) {
            u64 qv[6], kv[6];
#pragma unroll
            for (int a = 0; a < 6; a++)
                qv[a] = *(const u64*)&qs[(6 * ty + a) * 18 + 2 * k2];
#pragma unroll
            for (int d = 0; d < 6; d++)
                kv[d] = *(const u64*)&ks[(6 * tx + d) * 18 + 2 * k2];
#pragma unroll
            for (int a = 0; a < 6; a++)
#pragma unroll
                for (int d = 0; d < 6; d++)
                    fma2(A[a * 6 + d], qv[a], kv[d]);
        }
        __syncthreads();
    }

    float* Sp = g_S + bh * (96 * 96);
#pragma unroll
    for (int a = 0; a < 6; a++)
#pragma unroll
        for (int d = 0; d < 6; d++)
            atomicAdd(&Sp[(6 * ty + a) * 96 + (6 * tx + d)], hsum(A[a * 6 + d]));
}

// ---------------------------------------------------------------------------
// K4: fold norms + temperature, softmax rows (in-place in g_S)
// ---------------------------------------------------------------------------
__global__ void k_soft(const float* __restrict__ temp) {
    int bh = blockIdx.x;
    int b = bh >> 3, h = bh & 7;
    int r = threadIdx.x;                     // 0..95
    __shared__ float nk[96];

    float sq = g_norm2[(b * 96 + h * 6 + (r >> 4)) * 16 + (r & 15)];
    float nq = fmaxf(sqrtf(sq), 1e-12f);
    float sk = g_norm2[(b * 96 + 48 + h * 6 + (r >> 4)) * 16 + (r & 15)];
    nk[r] = fmaxf(sqrtf(sk), 1e-12f);
    __syncthreads();

    float t = temp[h];
    float* row = g_S + (bh * 96 + r) * 96;
    float vals[96];
    float m = -1e30f;
#pragma unroll
    for (int d = 0; d < 96; d++) {
        float a = row[d] / (nq * nk[d]) * t;
        vals[d] = a;
        m = fmaxf(m, a);
    }
    float ssum = 0.f;
#pragma unroll
    for (int d = 0; d < 96; d++) {
        float e = expf(vals[d] - m);
        vals[d] = e;
        ssum += e;
    }
    float inv = 1.f / ssum;
#pragma unroll
    for (int d = 0; d < 96; d++) row[d] = vals[d] * inv;
}

// ---------------------------------------------------------------------------
// K5: out = attn @ v, from_blocks layout; 6 rows x 8 cols per thread
// grid (128 col-tiles x 16 bh); 256 thr; smem: atT[96][97] + vs[96][128]
// ---------------------------------------------------------------------------
extern __shared__ float dynsm[];
__global__ void __launch_bounds__(256) k_av() {
    int bh = blockIdx.y;
    int b = bh >> 3, h = bh & 7;
    int tid = threadIdx.x;
    int ty = tid >> 4, tx = tid & 15;

    float* atT = dynsm;                  // 96*97 floats
    float* vs  = dynsm + 96 * 97;        // 96*128 floats

    const float* Sp = g_S + bh * 9216;
    for (int e = tid; e < 9216; e += 256) {
        int r = e / 96;
        int d = e - r * 96;
        atT[d * 97 + r] = Sp[e];
    }

    int i = blockIdx.x;                  // this block covers cols n = i*128 + [0,128)
    const float* vb = g_dw + (b * NC3 + 96 + h * 6) * HW;
    for (int e = tid; e < 12288; e += 256) {
        int d = e >> 7, c = e & 127;
        int dc = d >> 4, dh = (d >> 2) & 3, dwv = d & 3;
        vs[d * 128 + c] = vb[dc * HW + (4 * i + dh) * 512 + 4 * c + dwv];
    }
    __syncthreads();

    u64 A[24];
#pragma unroll
    for (int e = 0; e < 24; e++) A[e] = 0;

#pragma unroll 2
    for (int kd = 0; kd < 96; kd++) {
        const ulonglong2* vrow = (const ulonglong2*)&vs[kd * 128 + 8 * tx];
        ulonglong2 v0 = vrow[0];
        ulonglong2 v1 = vrow[1];
#pragma unroll
        for (int u = 0; u < 6; u++) {
            float a = atT[kd * 97 + 6 * ty + u];
            u64 asp = pk2(a, a);
            fma2(A[u * 4 + 0], asp, v0.x);
            fma2(A[u * 4 + 1], asp, v0.y);
            fma2(A[u * 4 + 2], asp, v1.x);
            fma2(A[u * 4 + 3], asp, v1.y);
        }
    }

    float* ob = g_ao + (b * NCH + h * 6) * HW;
#pragma unroll
    for (int u = 0; u < 6; u++) {
        int r = 6 * ty + u;
        int cc = r >> 4, nh = (r >> 2) & 3, nw = r & 3;
        int base = cc * HW + (4 * i + nh) * 512 + nw;
        int j = 8 * tx;
        float f[8];
        up2(A[u * 4 + 0], f[0], f[1]);
        up2(A[u * 4 + 1], f[2], f[3]);
        up2(A[u * 4 + 2], f[4], f[5]);
        up2(A[u * 4 + 3], f[6], f[7]);
#pragma unroll
        for (int c = 0; c < 8; c++)
            ob[base + 4 * (j + c)] = f[c];
    }
}

// ---------------------------------------------------------------------------
// K6: 1x1 proj 48 -> 48 into d_out, 2 pixels per thread
// ---------------------------------------------------------------------------
__global__ void __launch_bounds__(256) k_proj(const float* __restrict__ w,
                                              float* __restrict__ out) {
    __shared__ __align__(16) float ws[NCH * NCH];
    int tid = threadIdx.x;
    for (int e = tid; e < NCH * NCH; e += 256) ws[e] = w[e];
    __syncthreads();

    int p0 = blockIdx.x * 512 + tid;
    int b = p0 >> 18;
    int q = p0 & (HW - 1);
    const float* xb = g_ao + b * (NCH * HW) + q;

    u64 xp0[24], xp1[24];
#pragma unroll
    for (int j = 0; j < 24; j++) {
        xp0[j] = pk2(xb[(2 * j) * HW], xb[(2 * j + 1) * HW]);
        xp1[j] = pk2(xb[(2 * j) * HW + 256], xb[(2 * j + 1) * HW + 256]);
    }

    float* op = out + b * (NCH * HW) + q;
    const ulonglong2* w2 = (const ulonglong2*)ws;
    for (int oc = 0; oc < NCH; oc++) {
        const ulonglong2* wr = w2 + oc * 12;
        u64 a0 = 0, a1 = 0, a2 = 0, a3 = 0;
        u64 c0 = 0, c1 = 0, c2 = 0, c3 = 0;
#pragma unroll
        for (int j = 0; j < 12; j += 2) {
            ulonglong2 wa = wr[j];
            ulonglong2 wb = wr[j + 1];
            fma2(a0, wa.x, xp0[2 * j + 0]);
            fma2(a1, wa.y, xp0[2 * j + 1]);
            fma2(a2, wb.x, xp0[2 * j + 2]);
            fma2(a3, wb.y, xp0[2 * j + 3]);
            fma2(c0, wa.x, xp1[2 * j + 0]);
            fma2(c1, wa.y, xp1[2 * j + 1]);
            fma2(c2, wb.x, xp1[2 * j + 2]);
            fma2(c3, wb.y, xp1[2 * j + 3]);
        }
        op[oc * HW]       = hsum(a0) + hsum(a1) + hsum(a2) + hsum(a3);
        op[oc * HW + 256] = hsum(c0) + hsum(c1) + hsum(c2) + hsum(c3);
    }
}

// ---------------------------------------------------------------------------
extern "C" void kernel_launch(void* const* d_in, const int* in_sizes, int n_in,
                              void* d_out, int out_size) {
    const float* x     = (const float*)d_in[0];
    const float* qkvw  = (const float*)d_in[1];
    const float* dww   = (const float*)d_in[2];
    const float* projw = (const float*)d_in[3];
    const float* temp  = (const float*)d_in[4];
    float* out = (float*)d_out;

    cudaFuncSetAttribute(k_av, cudaFuncAttributeMaxDynamicSharedMemorySize,
                         (96 * 97 + 96 * 128) * 4);

    k_zero<<<576, 256>>>();
    k_qkv<<<1024, 256>>>(x, qkvw);
    k_dw<<<dim3(8, 64, NB_B * NC3), dim3(16, 8)>>>(dww);
    k_gram<<<dim3(64, NB_B * NHEADS), 256>>>();
    k_soft<<<NB_B * NHEADS, 96>>>(temp);
    k_av<<<dim3(128, NB_B * NHEADS), 256, (96 * 97 + 96 * 128) * 4>>>();
    k_proj<<<1024, 256>>>(projw, out);
}

// round 3
// speedup vs baseline: 1.0271x; 1.0271x over previous
#include <cuda_runtime.h>

// Problem constants
#define HW     262144        // 512*512
#define NB_B   2
#define NCH    48
#define NC3    144
#define NHEADS 8

// Scratch (device globals: no allocation allowed)
__device__ float g_qkv[NB_B * NC3 * HW];     // after 1x1 qkv conv
__device__ float g_dw[NB_B * NC3 * HW];      // after depthwise 3x3
__device__ float g_ao[NB_B * NCH * HW];      // after attn@V (from_blocks layout)
__device__ float g_norm2[NB_B * 96 * 16];    // per (b, q/k-ch, y%4, x%4) sum sq
__device__ float g_S[NB_B * NHEADS * 96 * 96]; // gram -> softmaxed attn

typedef unsigned long long u64;

__device__ __forceinline__ void fma2(u64& d, u64 a, u64 b) {
    asm("fma.rn.f32x2 %0, %1, %2, %0;" : "+l"(d) : "l"(a), "l"(b));
}
__device__ __forceinline__ u64 pk2(float lo, float hi) {
    u64 r; asm("mov.b64 %0, {%1, %2};" : "=l"(r) : "f"(lo), "f"(hi)); return r;
}
__device__ __forceinline__ float hsum(u64 v) {
    float lo, hi; asm("mov.b64 {%0, %1}, %2;" : "=f"(lo), "=f"(hi) : "l"(v)); return lo + hi;
}
__device__ __forceinline__ void up2(u64 v, float& lo, float& hi) {
    asm("mov.b64 {%0, %1}, %2;" : "=f"(lo), "=f"(hi) : "l"(v));
}

// ---------------------------------------------------------------------------
// K0: zero the accumulation buffers
// ---------------------------------------------------------------------------
__global__ void k_zero() {
    int i = blockIdx.x * 256 + threadIdx.x;
    if (i < NB_B * NHEADS * 96 * 96) g_S[i] = 0.f;
    if (i < NB_B * 96 * 16)          g_norm2[i] = 0.f;
}

// ---------------------------------------------------------------------------
// K1: 1x1 conv 48 -> 144 (per-pixel GEMV, f32x2 over ic pairs)  [R0 shape]
// ---------------------------------------------------------------------------
__global__ void __launch_bounds__(256) k_qkv(const float* __restrict__ x,
                                             const float* __restrict__ w) {
    __shared__ __align__(16) float ws[NC3 * NCH];
    int tid = threadIdx.x;
    for (int e = tid; e < NC3 * NCH; e += 256) ws[e] = w[e];
    __syncthreads();

    int p = blockIdx.x * 256 + tid;
    int b = p >> 18;
    int q = p & (HW - 1);
    const float* xb = x + b * (NCH * HW) + q;

    u64 xp[24];
#pragma unroll
    for (int j = 0; j < 24; j++)
        xp[j] = pk2(xb[(2 * j) * HW], xb[(2 * j + 1) * HW]);

    float* op = g_qkv + b * (NC3 * HW) + q;
    const ulonglong2* w2 = (const ulonglong2*)ws;
    for (int oc = 0; oc < NC3; oc++) {
        const ulonglong2* wr = w2 + oc * 12;
        u64 a0 = 0, a1 = 0, a2 = 0, a3 = 0;
#pragma unroll
        for (int j = 0; j < 12; j += 2) {
            ulonglong2 wa = wr[j];
            ulonglong2 wb = wr[j + 1];
            fma2(a0, wa.x, xp[2 * j + 0]);
            fma2(a1, wa.y, xp[2 * j + 1]);
            fma2(a2, wb.x, xp[2 * j + 2]);
            fma2(a3, wb.y, xp[2 * j + 3]);
        }
        op[oc * HW] = hsum(a0) + hsum(a1) + hsum(a2) + hsum(a3);
    }
}

// ---------------------------------------------------------------------------
// K2: depthwise 3x3 (zero pad) + fused q/k squared-norm accumulation
// ---------------------------------------------------------------------------
__global__ void __launch_bounds__(128) k_dw(const float* __restrict__ dww) {
    int ch = blockIdx.z % NC3;
    int b  = blockIdx.z / NC3;
    __shared__ float wk[9];
    __shared__ float sb[16];
    int tid = threadIdx.y * 16 + threadIdx.x;
    if (tid < 9)  wk[tid] = dww[ch * 9 + tid];
    if (tid < 16) sb[tid] = 0.f;
    __syncthreads();

    int x0 = (blockIdx.x * 16 + threadIdx.x) * 4;
    int y0 = blockIdx.y * 8 + threadIdx.y;
    const float* in = g_qkv + (b * NC3 + ch) * HW;

    float v[3][6];
#pragma unroll
    for (int r = 0; r < 3; r++) {
        int y = y0 + r - 1;
        if (y >= 0 && y < 512) {
            const float* rp = in + y * 512;
            float4 m = *(const float4*)(rp + x0);
            v[r][0] = (x0 > 0) ? rp[x0 - 1] : 0.f;
            v[r][1] = m.x; v[r][2] = m.y; v[r][3] = m.z; v[r][4] = m.w;
            v[r][5] = (x0 + 4 < 512) ? rp[x0 + 4] : 0.f;
        } else {
#pragma unroll
            for (int c = 0; c < 6; c++) v[r][c] = 0.f;
        }
    }

    float o[4];
#pragma unroll
    for (int px = 0; px < 4; px++) {
        float s = 0.f;
#pragma unroll
        for (int r = 0; r < 3; r++)
#pragma unroll
            for (int c = 0; c < 3; c++)
                s += wk[r * 3 + c] * v[r][px + c];
        o[px] = s;
    }
    float4 ov = make_float4(o[0], o[1], o[2], o[3]);
    *(float4*)(g_dw + (b * NC3 + ch) * HW + y0 * 512 + x0) = ov;

    if (ch < 96) {
#pragma unroll
        for (int px = 0; px < 4; px++) {
            float s = o[px] * o[px];
            s += __shfl_xor_sync(0xffffffffu, s, 8);
            s += __shfl_xor_sync(0xffffffffu, s, 4);
            s += __shfl_xor_sync(0xffffffffu, s, 2);
            s += __shfl_xor_sync(0xffffffffu, s, 1);
            if ((tid & 15) == 0) atomicAdd(&sb[(y0 & 3) * 4 + px], s);
        }
        __syncthreads();
        if (tid < 16) atomicAdd(&g_norm2[(b * 96 + ch) * 16 + tid], sb[tid]);
    }
}

// ---------------------------------------------------------------------------
// K3: raw gram  S[b,h,r,d] = sum_n q_r[n] * k_d[n]
// grid (64 chunks x 16 bh); 256 thr, 2 blocks/SM
// float4 fills (coalesced, 4 rows/load), double-buffered smem, 1 sync/step
// ---------------------------------------------------------------------------
__global__ void __launch_bounds__(256, 2) k_gram() {
    int bh = blockIdx.y;
    int b = bh >> 3, h = bh & 7;
    int chunk = blockIdx.x;                  // 256 block-columns, 16 steps
    __shared__ __align__(16) float qs[2][96 * 18];
    __shared__ __align__(16) float ks[2][96 * 18];
    int tid = threadIdx.x;
    int ty = tid >> 4, tx = tid & 15;

    const float* qb = g_dw + (b * NC3 + h * 6) * HW;
    const float* kb = qb + 48 * HW;

    // fill-thread geometry: e in [0,384): rg = e>>4 (cc*4+nh), col = e&15
    int rg0 = tid >> 4, col0 = tid & 15;
    int sbase0 = (rg0 >> 2) * HW + (rg0 & 3) * 512 + 4 * col0;
    int e1 = tid + 256;
    int rg1 = e1 >> 4, col1 = e1 & 15;
    int sbase1 = (rg1 >> 2) * HW + (rg1 & 3) * 512 + 4 * col1;
    bool has1 = tid < 128;

    u64 A[36];
#pragma unroll
    for (int e = 0; e < 36; e++) A[e] = 0;

    float4 rq0, rk0, rq1, rk1;
#define LDG_STEP(s)                                                          \
    {                                                                        \
        int dyn = (2 * chunk + ((s) >> 3)) * 2048 + ((s) & 7) * 64;          \
        rq0 = *(const float4*)(qb + sbase0 + dyn);                           \
        rk0 = *(const float4*)(kb + sbase0 + dyn);                           \
        if (has1) {                                                          \
            rq1 = *(const float4*)(qb + sbase1 + dyn);                       \
            rk1 = *(const float4*)(kb + sbase1 + dyn);                       \
        }                                                                    \
    }
#define STS_STEP(buf)                                                        \
    {                                                                        \
        float* qd = qs[buf]; float* kd = ks[buf];                            \
        qd[(4 * rg0 + 0) * 18 + col0] = rq0.x;                               \
        qd[(4 * rg0 + 1) * 18 + col0] = rq0.y;                               \
        qd[(4 * rg0 + 2) * 18 + col0] = rq0.z;                               \
        qd[(4 * rg0 + 3) * 18 + col0] = rq0.w;                               \
        kd[(4 * rg0 + 0) * 18 + col0] = rk0.x;                               \
        kd[(4 * rg0 + 1) * 18 + col0] = rk0.y;                               \
        kd[(4 * rg0 + 2) * 18 + col0] = rk0.z;                               \
        kd[(4 * rg0 + 3) * 18 + col0] = rk0.w;                               \
        if (has1) {                                                          \
            qd[(4 * rg1 + 0) * 18 + col1] = rq1.x;                           \
            qd[(4 * rg1 + 1) * 18 + col1] = rq1.y;                           \
            qd[(4 * rg1 + 2) * 18 + col1] = rq1.z;                           \
            qd[(4 * rg1 + 3) * 18 + col1] = rq1.w;                           \
            kd[(4 * rg1 + 0) * 18 + col1] = rk1.x;                           \
            kd[(4 * rg1 + 1) * 18 + col1] = rk1.y;                           \
            kd[(4 * rg1 + 2) * 18 + col1] = rk1.z;                           \
            kd[(4 * rg1 + 3) * 18 + col1] = rk1.w;                           \
        }                                                                    \
    }

    LDG_STEP(0);
    STS_STEP(0);
    __syncthreads();

    for (int s = 0; s < 16; s++) {
        int cur = s & 1;
        if (s < 15) LDG_STEP(s + 1);

        const float* qc = qs[cur];
        const float* kc = ks[cur];
#pragma unroll
        for (int k2 = 0; k2 < 8; k2++) {
            u64 qv[6], kv[6];
#pragma unroll
            for (int a = 0; a < 6; a++)
                qv[a] = *(const u64*)&qc[(6 * ty + a) * 18 + 2 * k2];
#pragma unroll
            for (int d = 0; d < 6; d++)
                kv[d] = *(const u64*)&kc[(6 * tx + d) * 18 + 2 * k2];
#pragma unroll
            for (int a = 0; a < 6; a++)
#pragma unroll
                for (int d = 0; d < 6; d++)
                    fma2(A[a * 6 + d], qv[a], kv[d]);
        }

        if (s < 15) STS_STEP(1 - cur);
        __syncthreads();
    }

    float* Sp = g_S + bh * (96 * 96);
#pragma unroll
    for (int a = 0; a < 6; a++)
#pragma unroll
        for (int d = 0; d < 6; d++)
            atomicAdd(&Sp[(6 * ty + a) * 96 + (6 * tx + d)], hsum(A[a * 6 + d]));
#undef LDG_STEP
#undef STS_STEP
}

// ---------------------------------------------------------------------------
// K4: fold norms + temperature, softmax rows (in-place in g_S)
// ---------------------------------------------------------------------------
__global__ void k_soft(const float* __restrict__ temp) {
    int bh = blockIdx.x;
    int b = bh >> 3, h = bh & 7;
    int r = threadIdx.x;                     // 0..95
    __shared__ float nk[96];

    float sq = g_norm2[(b * 96 + h * 6 + (r >> 4)) * 16 + (r & 15)];
    float nq = fmaxf(sqrtf(sq), 1e-12f);
    float sk = g_norm2[(b * 96 + 48 + h * 6 + (r >> 4)) * 16 + (r & 15)];
    nk[r] = fmaxf(sqrtf(sk), 1e-12f);
    __syncthreads();

    float t = temp[h];
    float* row = g_S + (bh * 96 + r) * 96;
    float vals[96];
    float m = -1e30f;
#pragma unroll
    for (int d = 0; d < 96; d++) {
        float a = row[d] / (nq * nk[d]) * t;
        vals[d] = a;
        m = fmaxf(m, a);
    }
    float ssum = 0.f;
#pragma unroll
    for (int d = 0; d < 96; d++) {
        float e = expf(vals[d] - m);
        vals[d] = e;
        ssum += e;
    }
    float inv = 1.f / ssum;
#pragma unroll
    for (int d = 0; d < 96; d++) row[d] = vals[d] * inv;
}

// ---------------------------------------------------------------------------
// K5: out = attn @ v, from_blocks layout; 6 rows x 4 cols/thread  [R0 shape]
// grid (256 col-tiles x 16 bh); 256 thr; V fill via coalesced float4
// ---------------------------------------------------------------------------
extern __shared__ float dynsm[];
__global__ void __launch_bounds__(256) k_av() {
    int bh = blockIdx.y;
    int b = bh >> 3, h = bh & 7;
    int tid = threadIdx.x;
    int ty = tid >> 4, tx = tid & 15;

    float* atT = dynsm;                  // 96*97 floats
    float* vs  = dynsm + 96 * 97;        // 96*64 floats

    const float* Sp = g_S + bh * 9216;
    for (int e = tid; e < 9216; e += 256) {
        int r = e / 96;
        int d = e - r * 96;
        atT[d * 97 + r] = Sp[e];
    }

    int n0 = blockIdx.x * 64;
    int i  = n0 >> 7;
    int j0 = n0 & 127;
    const float* vb = g_dw + (b * NC3 + 96 + h * 6) * HW;
    // 1536 float4 loads: e = rg*64 + c; rg = dc*4+dh; rows 4*rg+{0..3}, col c
    for (int e = tid; e < 1536; e += 256) {
        int rg = e >> 6, c = e & 63;
        int dc = rg >> 2, dh = rg & 3;
        float4 f = *(const float4*)(vb + dc * HW + (4 * i + dh) * 512 + 4 * (j0 + c));
        vs[(4 * rg + 0) * 64 + c] = f.x;
        vs[(4 * rg + 1) * 64 + c] = f.y;
        vs[(4 * rg + 2) * 64 + c] = f.z;
        vs[(4 * rg + 3) * 64 + c] = f.w;
    }
    __syncthreads();

    u64 A[12];
#pragma unroll
    for (int e = 0; e < 12; e++) A[e] = 0;

#pragma unroll 4
    for (int kd = 0; kd < 96; kd++) {
        float a[6];
#pragma unroll
        for (int u = 0; u < 6; u++) a[u] = atT[kd * 97 + 6 * ty + u];
        ulonglong2 v2 = *(const ulonglong2*)&vs[kd * 64 + 4 * tx];
#pragma unroll
        for (int u = 0; u < 6; u++) {
            u64 asp = pk2(a[u], a[u]);
            fma2(A[u * 2 + 0], asp, v2.x);
            fma2(A[u * 2 + 1], asp, v2.y);
        }
    }

    float* ob = g_ao + (b * NCH + h * 6) * HW;
#pragma unroll
    for (int u = 0; u < 6; u++) {
        int r = 6 * ty + u;
        int cc = r >> 4, nh = (r >> 2) & 3, nw = r & 3;
        int base = cc * HW + (4 * i + nh) * 512 + nw;
        float c0, c1, c2, c3;
        up2(A[u * 2 + 0], c0, c1);
        up2(A[u * 2 + 1], c2, c3);
        int j = j0 + 4 * tx;
        ob[base + 4 * (j + 0)] = c0;
        ob[base + 4 * (j + 1)] = c1;
        ob[base + 4 * (j + 2)] = c2;
        ob[base + 4 * (j + 3)] = c3;
    }
}

// ---------------------------------------------------------------------------
// K6: 1x1 proj 48 -> 48 into d_out  [R0 shape]
// ---------------------------------------------------------------------------
__global__ void __launch_bounds__(256) k_proj(const float* __restrict__ w,
                                              float* __restrict__ out) {
    __shared__ __align__(16) float ws[NCH * NCH];
    int tid = threadIdx.x;
    for (int e = tid; e < NCH * NCH; e += 256) ws[e] = w[e];
    __syncthreads();

    int p = blockIdx.x * 256 + tid;
    int b = p >> 18;
    int q = p & (HW - 1);
    const float* xb = g_ao + b * (NCH * HW) + q;

    u64 xp[24];
#pragma unroll
    for (int j = 0; j < 24; j++)
        xp[j] = pk2(xb[(2 * j) * HW], xb[(2 * j + 1) * HW]);

    float* op = out + b * (NCH * HW) + q;
    const ulonglong2* w2 = (const ulonglong2*)ws;
    for (int oc = 0; oc < NCH; oc++) {
        const ulonglong2* wr = w2 + oc * 12;
        u64 a0 = 0, a1 = 0, a2 = 0, a3 = 0;
#pragma unroll
        for (int j = 0; j < 12; j += 2) {
            ulonglong2 wa = wr[j];
            ulonglong2 wb = wr[j + 1];
            fma2(a0, wa.x, xp[2 * j + 0]);
            fma2(a1, wa.y, xp[2 * j + 1]);
            fma2(a2, wb.x, xp[2 * j + 2]);
            fma2(a3, wb.y, xp[2 * j + 3]);
        }
        op[oc * HW] = hsum(a0) + hsum(a1) + hsum(a2) + hsum(a3);
    }
}

// ---------------------------------------------------------------------------
extern "C" void kernel_launch(void* const* d_in, const int* in_sizes, int n_in,
                              void* d_out, int out_size) {
    const float* x     = (const float*)d_in[0];
    const float* qkvw  = (const float*)d_in[1];
    const float* dww   = (const float*)d_in[2];
    const float* projw = (const float*)d_in[3];
    const float* temp  = (const float*)d_in[4];
    float* out = (float*)d_out;

    cudaFuncSetAttribute(k_av, cudaFuncAttributeMaxDynamicSharedMemorySize,
                         (96 * 97 + 96 * 64) * 4);

    k_zero<<<576, 256>>>();
    k_qkv<<<2048, 256>>>(x, qkvw);
    k_dw<<<dim3(8, 64, NB_B * NC3), dim3(16, 8)>>>(dww);
    k_gram<<<dim3(64, NB_B * NHEADS), 256>>>();
    k_soft<<<NB_B * NHEADS, 96>>>(temp);
    k_av<<<dim3(256, NB_B * NHEADS), 256, (96 * 97 + 96 * 64) * 4>>>();
    k_proj<<<2048, 256>>>(projw, out);
}

// round 5
// speedup vs baseline: 1.0934x; 1.0646x over previous
#include <cuda_runtime.h>

// Problem constants
#define HW     262144        // 512*512
#define NB_B   2
#define NCH    48
#define NC3    144
#define NHEADS 8

// Scratch (device globals: no allocation allowed)
__device__ float g_qkv[NB_B * NC3 * HW];     // after 1x1 qkv conv
__device__ float g_dw[NB_B * NC3 * HW];      // after depthwise 3x3
__device__ float g_ao[NB_B * NCH * HW];      // after attn@V (from_blocks layout)
__device__ float g_norm2[NB_B * 96 * 16];    // per (b, q/k-ch, y%4, x%4) sum sq
__device__ float g_S[NB_B * NHEADS * 96 * 96]; // gram -> softmaxed attn

typedef unsigned long long u64;

__device__ __forceinline__ void fma2(u64& d, u64 a, u64 b) {
    asm("fma.rn.f32x2 %0, %1, %2, %0;" : "+l"(d) : "l"(a), "l"(b));
}
__device__ __forceinline__ u64 pk2(float lo, float hi) {
    u64 r; asm("mov.b64 %0, {%1, %2};" : "=l"(r) : "f"(lo), "f"(hi)); return r;
}
__device__ __forceinline__ float hsum(u64 v) {
    float lo, hi; asm("mov.b64 {%0, %1}, %2;" : "=f"(lo), "=f"(hi) : "l"(v)); return lo + hi;
}
__device__ __forceinline__ void up2(u64 v, float& lo, float& hi) {
    asm("mov.b64 {%0, %1}, %2;" : "=f"(lo), "=f"(hi) : "l"(v));
}

extern __shared__ float dynsm[];

// ---------------------------------------------------------------------------
// K0: zero the accumulation buffers
// ---------------------------------------------------------------------------
__global__ void k_zero() {
    int i = blockIdx.x * 256 + threadIdx.x;
    if (i < NB_B * NHEADS * 96 * 96) g_S[i] = 0.f;
    if (i < NB_B * 96 * 16)          g_norm2[i] = 0.f;
}

// ---------------------------------------------------------------------------
// K1: 1x1 conv 48 -> 144 as tiled GEMM: C[144 x 128px] = W[144x48] X[48x128]
// 256 thr; thread tile 9 oc x 8 px (f32x2 pixel pairs). dyn smem: W + X tile
// ---------------------------------------------------------------------------
__global__ void __launch_bounds__(256, 2) k_qkv(const float* __restrict__ x,
                                                const float* __restrict__ w) {
    float* Ws = dynsm;                 // 144*48 = 6912 floats
    float* Xs = dynsm + 6912;          // 48*128 = 6144 floats
    int tid = threadIdx.x;
    int ty = tid >> 4, tx = tid & 15;

    int b = blockIdx.x >> 11;                 // 2048 pixel-tiles per batch
    int q = (blockIdx.x & 2047) * 128;
    const float* xb = x + b * (NCH * HW) + q;

    // fill W (float4, coalesced; 6912 = 1728 float4)
    for (int e = tid * 4; e < 6912; e += 1024)
        *(float4*)&Ws[e] = *(const float4*)&w[e];
    // fill X tile: 1536 float4 loads
    for (int e = tid; e < 1536; e += 256) {
        int ch = e >> 5, c = e & 31;
        *(float4*)&Xs[ch * 128 + 4 * c] = *(const float4*)&xb[ch * HW + 4 * c];
    }
    __syncthreads();

    u64 acc[9][4];
#pragma unroll
    for (int j = 0; j < 9; j++)
#pragma unroll
        for (int i = 0; i < 4; i++) acc[j][i] = 0;

#pragma unroll 4
    for (int k = 0; k < 48; k++) {
        ulonglong2 xa = *(const ulonglong2*)&Xs[k * 128 + 8 * tx];
        ulonglong2 xc = *(const ulonglong2*)&Xs[k * 128 + 8 * tx + 4];
#pragma unroll
        for (int j = 0; j < 9; j++) {
            float wf = Ws[(9 * ty + j) * 48 + k];
            u64 wp = pk2(wf, wf);
            fma2(acc[j][0], wp, xa.x);
            fma2(acc[j][1], wp, xa.y);
            fma2(acc[j][2], wp, xc.x);
            fma2(acc[j][3], wp, xc.y);
        }
    }

    float* op = g_qkv + b * (NC3 * HW) + q + 8 * tx;
#pragma unroll
    for (int j = 0; j < 9; j++) {
        int oc = 9 * ty + j;
        float f0, f1, f2, f3, f4, f5, f6, f7;
        up2(acc[j][0], f0, f1);
        up2(acc[j][1], f2, f3);
        up2(acc[j][2], f4, f5);
        up2(acc[j][3], f6, f7);
        *(float4*)(op + oc * HW)     = make_float4(f0, f1, f2, f3);
        *(float4*)(op + oc * HW + 4) = make_float4(f4, f5, f6, f7);
    }
}

// ---------------------------------------------------------------------------
// K2: depthwise 3x3 (zero pad) + fused q/k squared-norm accumulation
// ---------------------------------------------------------------------------
__global__ void __launch_bounds__(128) k_dw(const float* __restrict__ dww) {
    int ch = blockIdx.z % NC3;
    int b  = blockIdx.z / NC3;
    __shared__ float wk[9];
    __shared__ float sb[16];
    int tid = threadIdx.y * 16 + threadIdx.x;
    if (tid < 9)  wk[tid] = dww[ch * 9 + tid];
    if (tid < 16) sb[tid] = 0.f;
    __syncthreads();

    int x0 = (blockIdx.x * 16 + threadIdx.x) * 4;
    int y0 = blockIdx.y * 8 + threadIdx.y;
    const float* in = g_qkv + (b * NC3 + ch) * HW;

    float v[3][6];
#pragma unroll
    for (int r = 0; r < 3; r++) {
        int y = y0 + r - 1;
        if (y >= 0 && y < 512) {
            const float* rp = in + y * 512;
            float4 m = *(const float4*)(rp + x0);
            v[r][0] = (x0 > 0) ? rp[x0 - 1] : 0.f;
            v[r][1] = m.x; v[r][2] = m.y; v[r][3] = m.z; v[r][4] = m.w;
            v[r][5] = (x0 + 4 < 512) ? rp[x0 + 4] : 0.f;
        } else {
#pragma unroll
            for (int c = 0; c < 6; c++) v[r][c] = 0.f;
        }
    }

    float o[4];
#pragma unroll
    for (int px = 0; px < 4; px++) {
        float s = 0.f;
#pragma unroll
        for (int r = 0; r < 3; r++)
#pragma unroll
            for (int c = 0; c < 3; c++)
                s += wk[r * 3 + c] * v[r][px + c];
        o[px] = s;
    }
    float4 ov = make_float4(o[0], o[1], o[2], o[3]);
    *(float4*)(g_dw + (b * NC3 + ch) * HW + y0 * 512 + x0) = ov;

    if (ch < 96) {
#pragma unroll
        for (int px = 0; px < 4; px++) {
            float s = o[px] * o[px];
            s += __shfl_xor_sync(0xffffffffu, s, 8);
            s += __shfl_xor_sync(0xffffffffu, s, 4);
            s += __shfl_xor_sync(0xffffffffu, s, 2);
            s += __shfl_xor_sync(0xffffffffu, s, 1);
            if ((tid & 15) == 0) atomicAdd(&sb[(y0 & 3) * 4 + px], s);
        }
        __syncthreads();
        if (tid < 16) atomicAdd(&g_norm2[(b * 96 + ch) * 16 + tid], sb[tid]);
    }
}

// ---------------------------------------------------------------------------
// K3: raw gram [R1 version: scalar fills, register prefetch, 2 blocks/SM]
// ---------------------------------------------------------------------------
__global__ void __launch_bounds__(256, 2) k_gram() {
    int bh = blockIdx.y;
    int b = bh >> 3, h = bh & 7;
    int chunk = blockIdx.x;                  // 256 columns per chunk, 16 steps
    __shared__ __align__(16) float qs[96 * 18];
    __shared__ __align__(16) float ks[96 * 18];
    int tid = threadIdx.x;
    int ty = tid >> 4, tx = tid & 15;
    int kk = tid & 15;

    const float* qb = g_dw + (b * NC3 + h * 6) * HW;
    const float* kb = qb + 48 * HW;

    int offs[6];
#pragma unroll
    for (int u = 0; u < 6; u++) {
        int row = u * 16 + ty;
        int cc = row >> 4, nh = (row >> 2) & 3, nw = row & 3;
        offs[u] = cc * HW + nh * 512 + nw + 4 * kk;
    }

    u64 A[36];
#pragma unroll
    for (int e = 0; e < 36; e++) A[e] = 0;

    float rq[6], rk[6];
    {
        int so = (2 * chunk) * 2048;         // step 0
#pragma unroll
        for (int u = 0; u < 6; u++) {
            rq[u] = qb[offs[u] + so];
            rk[u] = kb[offs[u] + so];
        }
    }

    for (int s = 0; s < 16; s++) {
#pragma unroll
        for (int u = 0; u < 6; u++) {
            int sidx = (u * 16 + ty) * 18 + kk;
            qs[sidx] = rq[u];
            ks[sidx] = rk[u];
        }
        __syncthreads();
        if (s < 15) {
            int s1 = s + 1;
            int so1 = (2 * chunk + (s1 >> 3)) * 2048 + (s1 & 7) * 64;
#pragma unroll
            for (int u = 0; u < 6; u++) {
                rq[u] = qb[offs[u] + so1];
                rk[u] = kb[offs[u] + so1];
            }
        }
#pragma unroll
        for (int k2 = 0; k2 < 8; k2++) {
            u64 qv[6], kv[6];
#pragma unroll
            for (int a = 0; a < 6; a++)
                qv[a] = *(const u64*)&qs[(6 * ty + a) * 18 + 2 * k2];
#pragma unroll
            for (int d = 0; d < 6; d++)
                kv[d] = *(const u64*)&ks[(6 * tx + d) * 18 + 2 * k2];
#pragma unroll
            for (int a = 0; a < 6; a++)
#pragma unroll
                for (int d = 0; d < 6; d++)
                    fma2(A[a * 6 + d], qv[a], kv[d]);
        }
        __syncthreads();
    }

    float* Sp = g_S + bh * (96 * 96);
#pragma unroll
    for (int a = 0; a < 6; a++)
#pragma unroll
        for (int d = 0; d < 6; d++)
            atomicAdd(&Sp[(6 * ty + a) * 96 + (6 * tx + d)], hsum(A[a * 6 + d]));
}

// ---------------------------------------------------------------------------
// K4: fold norms + temperature, softmax rows (in-place in g_S)
// ---------------------------------------------------------------------------
__global__ void k_soft(const float* __restrict__ temp) {
    int bh = blockIdx.x;
    int b = bh >> 3, h = bh & 7;
    int r = threadIdx.x;                     // 0..95
    __shared__ float nk[96];

    float sq = g_norm2[(b * 96 + h * 6 + (r >> 4)) * 16 + (r & 15)];
    float nq = fmaxf(sqrtf(sq), 1e-12f);
    float sk = g_norm2[(b * 96 + 48 + h * 6 + (r >> 4)) * 16 + (r & 15)];
    nk[r] = fmaxf(sqrtf(sk), 1e-12f);
    __syncthreads();

    float t = temp[h];
    float* row = g_S + (bh * 96 + r) * 96;
    float vals[96];
    float m = -1e30f;
#pragma unroll
    for (int d = 0; d < 96; d++) {
        float a = row[d] / (nq * nk[d]) * t;
        vals[d] = a;
        m = fmaxf(m, a);
    }
    float ssum = 0.f;
#pragma unroll
    for (int d = 0; d < 96; d++) {
        float e = expf(vals[d] - m);
        vals[d] = e;
        ssum += e;
    }
    float inv = 1.f / ssum;
#pragma unroll
    for (int d = 0; d < 96; d++) row[d] = vals[d] * inv;
}

// ---------------------------------------------------------------------------
// K5: out = attn @ v, from_blocks layout; 6 rows x 4 cols/thread
// grid (256 col-tiles x 16 bh); 256 thr; V fill via coalesced float4
// ---------------------------------------------------------------------------
__global__ void __launch_bounds__(256) k_av() {
    int bh = blockIdx.y;
    int b = bh >> 3, h = bh & 7;
    int tid = threadIdx.x;
    int ty = tid >> 4, tx = tid & 15;

    float* atT = dynsm;                  // 96*97 floats
    float* vs  = dynsm + 96 * 97;        // 96*64 floats

    const float* Sp = g_S + bh * 9216;
    for (int e = tid; e < 9216; e += 256) {
        int r = e / 96;
        int d = e - r * 96;
        atT[d * 97 + r] = Sp[e];
    }

    int n0 = blockIdx.x * 64;
    int i  = n0 >> 7;
    int j0 = n0 & 127;
    const float* vb = g_dw + (b * NC3 + 96 + h * 6) * HW;
    for (int e = tid; e < 1536; e += 256) {
        int rg = e >> 6, c = e & 63;
        int dc = rg >> 2, dh = rg & 3;
        float4 f = *(const float4*)(vb + dc * HW + (4 * i + dh) * 512 + 4 * (j0 + c));
        vs[(4 * rg + 0) * 64 + c] = f.x;
        vs[(4 * rg + 1) * 64 + c] = f.y;
        vs[(4 * rg + 2) * 64 + c] = f.z;
        vs[(4 * rg + 3) * 64 + c] = f.w;
    }
    __syncthreads();

    u64 A[12];
#pragma unroll
    for (int e = 0; e < 12; e++) A[e] = 0;

#pragma unroll 4
    for (int kd = 0; kd < 96; kd++) {
        float a[6];
#pragma unroll
        for (int u = 0; u < 6; u++) a[u] = atT[kd * 97 + 6 * ty + u];
        ulonglong2 v2 = *(const ulonglong2*)&vs[kd * 64 + 4 * tx];
#pragma unroll
        for (int u = 0; u < 6; u++) {
            u64 asp = pk2(a[u], a[u]);
            fma2(A[u * 2 + 0], asp, v2.x);
            fma2(A[u * 2 + 1], asp, v2.y);
        }
    }

    float* ob = g_ao + (b * NCH + h * 6) * HW;
#pragma unroll
    for (int u = 0; u < 6; u++) {
        int r = 6 * ty + u;
        int cc = r >> 4, nh = (r >> 2) & 3, nw = r & 3;
        int base = cc * HW + (4 * i + nh) * 512 + nw;
        float c0, c1, c2, c3;
        up2(A[u * 2 + 0], c0, c1);
        up2(A[u * 2 + 1], c2, c3);
        int j = j0 + 4 * tx;
        ob[base + 4 * (j + 0)] = c0;
        ob[base + 4 * (j + 1)] = c1;
        ob[base + 4 * (j + 2)] = c2;
        ob[base + 4 * (j + 3)] = c3;
    }
}

// ---------------------------------------------------------------------------
// K6: 1x1 proj 48 -> 48 as tiled GEMM; thread tile 3 oc x 8 px
// ---------------------------------------------------------------------------
__global__ void __launch_bounds__(256, 2) k_proj(const float* __restrict__ w,
                                                 float* __restrict__ out) {
    __shared__ __align__(16) float Ws[NCH * NCH];     // 2304 floats
    __shared__ __align__(16) float Xs[NCH * 128];     // 6144 floats
    int tid = threadIdx.x;
    int ty = tid >> 4, tx = tid & 15;

    int b = blockIdx.x >> 11;
    int q = (blockIdx.x & 2047) * 128;
    const float* xb = g_ao + b * (NCH * HW) + q;

    for (int e = tid * 4; e < NCH * NCH; e += 1024)
        *(float4*)&Ws[e] = *(const float4*)&w[e];
    for (int e = tid; e < 1536; e += 256) {
        int ch = e >> 5, c = e & 31;
        *(float4*)&Xs[ch * 128 + 4 * c] = *(const float4*)&xb[ch * HW + 4 * c];
    }
    __syncthreads();

    u64 acc[3][4];
#pragma unroll
    for (int j = 0; j < 3; j++)
#pragma unroll
        for (int i = 0; i < 4; i++) acc[j][i] = 0;

#pragma unroll 4
    for (int k = 0; k < 48; k++) {
        ulonglong2 xa = *(const ulonglong2*)&Xs[k * 128 + 8 * tx];
        ulonglong2 xc = *(const ulonglong2*)&Xs[k * 128 + 8 * tx + 4];
#pragma unroll
        for (int j = 0; j < 3; j++) {
            float wf = Ws[(3 * ty + j) * 48 + k];
            u64 wp = pk2(wf, wf);
            fma2(acc[j][0], wp, xa.x);
            fma2(acc[j][1], wp, xa.y);
            fma2(acc[j][2], wp, xc.x);
            fma2(acc[j][3], wp, xc.y);
        }
    }

    float* op = out + b * (NCH * HW) + q + 8 * tx;
#pragma unroll
    for (int j = 0; j < 3; j++) {
        int oc = 3 * ty + j;
        float f0, f1, f2, f3, f4, f5, f6, f7;
        up2(acc[j][0], f0, f1);
        up2(acc[j][1], f2, f3);
        up2(acc[j][2], f4, f5);
        up2(acc[j][3], f6, f7);
        *(float4*)(op + oc * HW)     = make_float4(f0, f1, f2, f3);
        *(float4*)(op + oc * HW + 4) = make_float4(f4, f5, f6, f7);
    }
}

// ---------------------------------------------------------------------------
extern "C" void kernel_launch(void* const* d_in, const int* in_sizes, int n_in,
                              void* d_out, int out_size) {
    const float* x     = (const float*)d_in[0];
    const float* qkvw  = (const float*)d_in[1];
    const float* dww   = (const float*)d_in[2];
    const float* projw = (const float*)d_in[3];
    const float* temp  = (const float*)d_in[4];
    float* out = (float*)d_out;

    cudaFuncSetAttribute(k_qkv, cudaFuncAttributeMaxDynamicSharedMemorySize,
                         (6912 + 6144) * 4);
    cudaFuncSetAttribute(k_av, cudaFuncAttributeMaxDynamicSharedMemorySize,
                         (96 * 97 + 96 * 64) * 4);

    k_zero<<<576, 256>>>();
    k_qkv<<<4096, 256, (6912 + 6144) * 4>>>(x, qkvw);
    k_dw<<<dim3(8, 64, NB_B * NC3), dim3(16, 8)>>>(dww);
    k_gram<<<dim3(64, NB_B * NHEADS), 256>>>();
    k_soft<<<NB_B * NHEADS, 96>>>(temp);
    k_av<<<dim3(256, NB_B * NHEADS), 256, (96 * 97 + 96 * 64) * 4>>>();
    k_proj<<<4096, 256>>>(projw, out);
}